// round 11
// baseline (speedup 1.0000x reference)
#include <cuda_runtime.h>
#include <cuda_fp16.h>

// LightGCN propagation via on-device CSR build + register-accumulated SpMM.
// U=100000, I=50000, N=150000, D=64, nnz=4M (symmetric), n_layers=3 (fixed).
//
// Round 11: SpMM ran ~81us/layer vs ~61us L2 floor; gap attributed to
// intra-warp degree divergence (4 rows per warp ran at max-degree). Now ONE
// row per 32-lane warp (lane owns one half2, 128B/row gather unchanged), and
// edge (col,val) packed into one int2 (halves scatter sector traffic, makes
// the SpMM edge load a single 8B warp-uniform broadcast).

#define DIM 64
#define MAX_ND  9600000   // 150000 * 64
#define MAX_N   150016
#define MAX_NNZ 4000000
#define SCAN_B  1024

__device__ __half g_bufA[MAX_ND];
__device__ __half g_bufB[MAX_ND];
__device__ float  g_acc[MAX_ND];
__device__ int    g_counts[MAX_N];
__device__ int    g_rowptr[MAX_N + 1];
__device__ int    g_off[MAX_N];
__device__ int    g_bsum[SCAN_B];
__device__ int    g_boff[SCAN_B];
__device__ int2   g_edge[MAX_NNZ];   // (col, float_as_int(val))

// ---------------- init: bufA = fp16(concat(ue, ie)); acc = fp32 same --------
__global__ void lgcn_init(const float4* __restrict__ ue,
                          const float4* __restrict__ ie,
                          int u4, int n4) {
    int i = blockIdx.x * blockDim.x + threadIdx.x;
    if (i >= n4) return;
    float4 v = (i < u4) ? ue[i] : ie[i - u4];
    ((float4*)g_acc)[i] = v;
    half2 h0 = __floats2half2_rn(v.x, v.y);
    half2 h1 = __floats2half2_rn(v.z, v.w);
    ((half2*)g_bufA)[2 * i]     = h0;
    ((half2*)g_bufA)[2 * i + 1] = h1;
}

// ---------------- CSR build ------------------------------------------------
__global__ void csr_zero(int n_nodes) {
    int i = blockIdx.x * blockDim.x + threadIdx.x;
    if (i < n_nodes) g_counts[i] = 0;
}

__global__ void csr_hist(const int* __restrict__ rows, int nnz) {
    int e = blockIdx.x * blockDim.x + threadIdx.x;
    if (e < nnz) atomicAdd(&g_counts[rows[e]], 1);
}

// two-level parallel exclusive scan of g_counts -> g_rowptr / g_off
__global__ void csr_scan1(int n_nodes) {
    __shared__ int s[SCAN_B];
    int tid = threadIdx.x;
    int i = blockIdx.x * SCAN_B + tid;
    int v = (i < n_nodes) ? g_counts[i] : 0;
    s[tid] = v;
    __syncthreads();
    for (int o = 1; o < SCAN_B; o <<= 1) {
        int x = s[tid];
        int a = (tid >= o) ? s[tid - o] : 0;
        __syncthreads();
        s[tid] = x + a;
        __syncthreads();
    }
    if (i < n_nodes) g_off[i] = s[tid] - v;     // local exclusive
    if (tid == SCAN_B - 1) g_bsum[blockIdx.x] = s[SCAN_B - 1];
}

__global__ void csr_scan2(int nblocks) {
    __shared__ int s[SCAN_B];
    int t = threadIdx.x;
    int v = (t < nblocks) ? g_bsum[t] : 0;
    s[t] = v;
    __syncthreads();
    for (int o = 1; o < SCAN_B; o <<= 1) {
        int x = s[t];
        int a = (t >= o) ? s[t - o] : 0;
        __syncthreads();
        s[t] = x + a;
        __syncthreads();
    }
    g_boff[t] = s[t] - v;                       // exclusive block offset
}

__global__ void csr_scan3(int n_nodes, int nnz) {
    int i = blockIdx.x * SCAN_B + threadIdx.x;
    if (i < n_nodes) {
        int r = g_off[i] + g_boff[blockIdx.x];
        g_rowptr[i] = r;
        g_off[i]    = r;
    }
    if (i == 0) g_rowptr[n_nodes] = nnz;
}

__global__ void csr_scatter(const int* __restrict__ rows,
                            const int* __restrict__ cols,
                            const float* __restrict__ vals,
                            int nnz) {
    int e = blockIdx.x * blockDim.x + threadIdx.x;
    if (e >= nnz) return;
    int r = rows[e];
    int pos = atomicAdd(&g_off[r], 1);
    g_edge[pos] = make_int2(cols[e], __float_as_int(vals[e]));
}

// ---------------- CSR SpMM, fp16 gather, fp32 accumulation -----------------
// ONE row per 32-lane warp; lane li owns half2 slot li (dims 2li, 2li+1).
// Gather per edge = 32 x 4B = 128B coalesced. Edge load = 8B broadcast.
// swap==0: read bufA, write bufB.  swap==1: read bufB, write bufA.
// out==nullptr: nxt[row]=fp16(s), acc[row]+=s.  out!=nullptr: out=(acc+s)/4.
__global__ void lgcn_spmm_csr(int swap, int n_nodes, float2* __restrict__ out) {
    int t  = blockIdx.x * blockDim.x + threadIdx.x;
    int g  = t >> 5;
    int li = t & 31;
    if (g >= n_nodes) return;

    const half2* cur = (const half2*)(swap ? g_bufB : g_bufA);
    half2*       nxt = (half2*)(swap ? g_bufA : g_bufB);

    int beg = g_rowptr[g];
    int end = g_rowptr[g + 1];

    float s0 = 0.f, s1 = 0.f;
    #pragma unroll 4
    for (int e = beg; e < end; e++) {
        int2  ev = __ldg(&g_edge[e]);
        float v  = __int_as_float(ev.y);
        float2 f = __half22float2(__ldg(&cur[(size_t)ev.x * 32 + li]));
        s0 += v * f.x;
        s1 += v * f.y;
    }

    size_t idx = (size_t)g * 32 + li;
    float2 a = ((float2*)g_acc)[idx];
    if (out == nullptr) {
        nxt[idx] = __floats2half2_rn(s0, s1);
        ((float2*)g_acc)[idx] = make_float2(a.x + s0, a.y + s1);
    } else {
        out[idx] = make_float2((a.x + s0) * 0.25f, (a.y + s1) * 0.25f);
    }
}

// ---------------- launch ---------------------------------------------------
extern "C" void kernel_launch(void* const* d_in, const int* in_sizes, int n_in,
                              void* d_out, int out_size) {
    const float* ue   = (const float*)d_in[0];
    const float* ie   = (const float*)d_in[1];
    const int*   rows = (const int*)d_in[2];
    const int*   cols = (const int*)d_in[3];
    const float* vals = (const float*)d_in[4];
    // d_in[5] is n_layers (device scalar == 3, fixed by the problem setup).

    int nnz     = in_sizes[2];
    int u4      = in_sizes[0] / 4;
    int n4      = (in_sizes[0] + in_sizes[1]) / 4;
    int n_nodes = (in_sizes[0] + in_sizes[1]) / DIM;

    const int T = 256;
    int nb_n4   = (n4 + T - 1) / T;
    int nb_nnz  = (nnz + T - 1) / T;
    int nb_nod  = (n_nodes + T - 1) / T;
    long long spmm_threads = (long long)n_nodes * 32ll;
    int nb_spm  = (int)((spmm_threads + T - 1) / T);
    int nb_scan = (n_nodes + SCAN_B - 1) / SCAN_B;

    lgcn_init<<<nb_n4, T>>>((const float4*)ue, (const float4*)ie, u4, n4);

    csr_zero<<<nb_nod, T>>>(n_nodes);
    csr_hist<<<nb_nnz, T>>>(rows, nnz);
    csr_scan1<<<nb_scan, SCAN_B>>>(n_nodes);
    csr_scan2<<<1, SCAN_B>>>(nb_scan);
    csr_scan3<<<nb_scan, SCAN_B>>>(n_nodes, nnz);
    csr_scatter<<<nb_nnz, T>>>(rows, cols, vals, nnz);

    lgcn_spmm_csr<<<nb_spm, T>>>(0, n_nodes, nullptr);            // layer 1: A->B
    lgcn_spmm_csr<<<nb_spm, T>>>(1, n_nodes, nullptr);            // layer 2: B->A
    lgcn_spmm_csr<<<nb_spm, T>>>(0, n_nodes, (float2*)d_out);     // layer 3 + mean
}

// round 13
// speedup vs baseline: 1.0572x; 1.0572x over previous
#include <cuda_runtime.h>
#include <cuda_fp16.h>

// LightGCN propagation via on-device CSR build + register-accumulated SpMM.
// U=100000, I=50000, N=150000, D=64, nnz=4M (symmetric), n_layers=3 (fixed).
//
// Round 13: resubmit of round-12 kernel (container infra failure, no kernel
// signal). Round-10 SpMM layout (8 lanes/row, int4 fp16 gathers) + degree-
// sorted row permutation (counting sort) so the 4 rows sharing a warp have
// similar degrees, removing intra-warp trip-count divergence.

#define DIM 64
#define MAX_ND  9600000   // 150000 * 64
#define MAX_N   150016
#define MAX_NNZ 4000000
#define SCAN_B  1024
#define DBINS   1024

__device__ __half g_bufA[MAX_ND];
__device__ __half g_bufB[MAX_ND];
__device__ float  g_acc[MAX_ND];
__device__ int    g_counts[MAX_N];
__device__ int    g_rowptr[MAX_N + 1];
__device__ int    g_off[MAX_N];
__device__ int    g_bsum[SCAN_B];
__device__ int    g_boff[SCAN_B];
__device__ int    g_ecol[MAX_NNZ];
__device__ float  g_eval[MAX_NNZ];
__device__ int    g_dhist[DBINS];
__device__ int    g_dcur[DBINS];
__device__ int    g_perm[MAX_N];

// ---------------- init: bufA = fp16(concat(ue, ie)); acc = fp32 same --------
__global__ void lgcn_init(const float4* __restrict__ ue,
                          const float4* __restrict__ ie,
                          int u4, int n4) {
    int i = blockIdx.x * blockDim.x + threadIdx.x;
    if (i >= n4) return;
    float4 v = (i < u4) ? ue[i] : ie[i - u4];
    ((float4*)g_acc)[i] = v;
    half2 h0 = __floats2half2_rn(v.x, v.y);
    half2 h1 = __floats2half2_rn(v.z, v.w);
    ((half2*)g_bufA)[2 * i]     = h0;
    ((half2*)g_bufA)[2 * i + 1] = h1;
}

// ---------------- CSR build ------------------------------------------------
__global__ void csr_zero(int n_nodes) {
    int i = blockIdx.x * blockDim.x + threadIdx.x;
    if (i < n_nodes) g_counts[i] = 0;
    if (i < DBINS)   g_dhist[i]  = 0;
}

__global__ void csr_hist(const int* __restrict__ rows, int nnz) {
    int e = blockIdx.x * blockDim.x + threadIdx.x;
    if (e < nnz) atomicAdd(&g_counts[rows[e]], 1);
}

// two-level parallel exclusive scan of g_counts -> g_rowptr / g_off
__global__ void csr_scan1(int n_nodes) {
    __shared__ int s[SCAN_B];
    int tid = threadIdx.x;
    int i = blockIdx.x * SCAN_B + tid;
    int v = (i < n_nodes) ? g_counts[i] : 0;
    s[tid] = v;
    __syncthreads();
    for (int o = 1; o < SCAN_B; o <<= 1) {
        int x = s[tid];
        int a = (tid >= o) ? s[tid - o] : 0;
        __syncthreads();
        s[tid] = x + a;
        __syncthreads();
    }
    if (i < n_nodes) g_off[i] = s[tid] - v;     // local exclusive
    if (tid == SCAN_B - 1) g_bsum[blockIdx.x] = s[SCAN_B - 1];
}

__global__ void csr_scan2(int nblocks) {
    __shared__ int s[SCAN_B];
    int t = threadIdx.x;
    int v = (t < nblocks) ? g_bsum[t] : 0;
    s[t] = v;
    __syncthreads();
    for (int o = 1; o < SCAN_B; o <<= 1) {
        int x = s[t];
        int a = (t >= o) ? s[t - o] : 0;
        __syncthreads();
        s[t] = x + a;
        __syncthreads();
    }
    g_boff[t] = s[t] - v;                       // exclusive block offset
}

__global__ void csr_scan3(int n_nodes, int nnz) {
    int i = blockIdx.x * SCAN_B + threadIdx.x;
    if (i < n_nodes) {
        int r = g_off[i] + g_boff[blockIdx.x];
        g_rowptr[i] = r;
        g_off[i]    = r;
    }
    if (i == 0) g_rowptr[n_nodes] = nnz;
}

__global__ void csr_scatter(const int* __restrict__ rows,
                            const int* __restrict__ cols,
                            const float* __restrict__ vals,
                            int nnz) {
    int e = blockIdx.x * blockDim.x + threadIdx.x;
    if (e >= nnz) return;
    int r = rows[e];
    int pos = atomicAdd(&g_off[r], 1);
    g_ecol[pos] = cols[e];
    g_eval[pos] = vals[e];
}

// ---------------- degree counting sort -> g_perm ---------------------------
__global__ void dsort_hist(int n_nodes) {
    int i = blockIdx.x * blockDim.x + threadIdx.x;
    if (i >= n_nodes) return;
    int b = g_counts[i]; if (b > DBINS - 1) b = DBINS - 1;
    atomicAdd(&g_dhist[b], 1);
}

__global__ void dsort_scan() {   // single block, 1024 bins
    __shared__ int s[DBINS];
    int t = threadIdx.x;
    int v = g_dhist[t];
    s[t] = v;
    __syncthreads();
    for (int o = 1; o < DBINS; o <<= 1) {
        int x = s[t];
        int a = (t >= o) ? s[t - o] : 0;
        __syncthreads();
        s[t] = x + a;
        __syncthreads();
    }
    g_dcur[t] = s[t] - v;        // exclusive offsets, doubles as cursor
}

__global__ void dsort_scatter(int n_nodes) {
    int i = blockIdx.x * blockDim.x + threadIdx.x;
    if (i >= n_nodes) return;
    int b = g_counts[i]; if (b > DBINS - 1) b = DBINS - 1;
    int pos = atomicAdd(&g_dcur[b], 1);
    g_perm[pos] = i;
}

// ---------------- CSR SpMM, fp16 gather, fp32 accumulation -----------------
// One row per 8-lane group, rows taken via degree-sorted perm so warps get
// similar-degree rows. Lane li owns dims [li*8, li*8+8) = one 16B int4.
// swap==0: read bufA, write bufB.  swap==1: read bufB, write bufA.
// out==nullptr: nxt[row]=fp16(s), acc[row]+=s.  out!=nullptr: out=(acc+s)/4.
__global__ void lgcn_spmm_csr(int swap, int n_nodes, float4* __restrict__ out) {
    int t  = blockIdx.x * blockDim.x + threadIdx.x;
    int gi = t >> 3;
    int li = t & 7;
    if (gi >= n_nodes) return;
    int g = g_perm[gi];

    const int4* cur = (const int4*)(swap ? g_bufB : g_bufA);
    int4*       nxt = (int4*)(swap ? g_bufA : g_bufB);

    int beg = g_rowptr[g];
    int end = g_rowptr[g + 1];

    float s0 = 0.f, s1 = 0.f, s2 = 0.f, s3 = 0.f;
    float s4 = 0.f, s5 = 0.f, s6 = 0.f, s7 = 0.f;
    #pragma unroll 4
    for (int e = beg; e < end; e++) {
        int   c = g_ecol[e];
        float v = g_eval[e];
        int4 raw = __ldg(&cur[(size_t)c * 8 + li]);
        float2 f0 = __half22float2(*(half2*)&raw.x);
        float2 f1 = __half22float2(*(half2*)&raw.y);
        float2 f2 = __half22float2(*(half2*)&raw.z);
        float2 f3 = __half22float2(*(half2*)&raw.w);
        s0 += v * f0.x; s1 += v * f0.y;
        s2 += v * f1.x; s3 += v * f1.y;
        s4 += v * f2.x; s5 += v * f2.y;
        s6 += v * f3.x; s7 += v * f3.y;
    }

    size_t fidx = ((size_t)g * DIM + (size_t)li * 8) / 4;  // float4 index
    float4 a0 = ((float4*)g_acc)[fidx];
    float4 a1 = ((float4*)g_acc)[fidx + 1];

    if (out == nullptr) {
        int4 packed;
        half2 h0 = __floats2half2_rn(s0, s1);
        half2 h1 = __floats2half2_rn(s2, s3);
        half2 h2 = __floats2half2_rn(s4, s5);
        half2 h3 = __floats2half2_rn(s6, s7);
        packed.x = *(int*)&h0; packed.y = *(int*)&h1;
        packed.z = *(int*)&h2; packed.w = *(int*)&h3;
        nxt[(size_t)g * 8 + li] = packed;
        ((float4*)g_acc)[fidx]     = make_float4(a0.x + s0, a0.y + s1,
                                                 a0.z + s2, a0.w + s3);
        ((float4*)g_acc)[fidx + 1] = make_float4(a1.x + s4, a1.y + s5,
                                                 a1.z + s6, a1.w + s7);
    } else {
        out[fidx]     = make_float4((a0.x + s0) * 0.25f, (a0.y + s1) * 0.25f,
                                    (a0.z + s2) * 0.25f, (a0.w + s3) * 0.25f);
        out[fidx + 1] = make_float4((a1.x + s4) * 0.25f, (a1.y + s5) * 0.25f,
                                    (a1.z + s6) * 0.25f, (a1.w + s7) * 0.25f);
    }
}

// ---------------- launch ---------------------------------------------------
extern "C" void kernel_launch(void* const* d_in, const int* in_sizes, int n_in,
                              void* d_out, int out_size) {
    const float* ue   = (const float*)d_in[0];
    const float* ie   = (const float*)d_in[1];
    const int*   rows = (const int*)d_in[2];
    const int*   cols = (const int*)d_in[3];
    const float* vals = (const float*)d_in[4];
    // d_in[5] is n_layers (device scalar == 3, fixed by the problem setup).

    int nnz     = in_sizes[2];
    int u4      = in_sizes[0] / 4;
    int n4      = (in_sizes[0] + in_sizes[1]) / 4;
    int n_nodes = (in_sizes[0] + in_sizes[1]) / DIM;

    const int T = 256;
    int nb_n4   = (n4 + T - 1) / T;
    int nb_nnz  = (nnz + T - 1) / T;
    int nb_nod  = (n_nodes + T - 1) / T;
    int nb_spm  = (n_nodes * 8 + T - 1) / T;
    int nb_scan = (n_nodes + SCAN_B - 1) / SCAN_B;

    lgcn_init<<<nb_n4, T>>>((const float4*)ue, (const float4*)ie, u4, n4);

    csr_zero<<<nb_nod, T>>>(n_nodes);
    csr_hist<<<nb_nnz, T>>>(rows, nnz);
    csr_scan1<<<nb_scan, SCAN_B>>>(n_nodes);
    csr_scan2<<<1, SCAN_B>>>(nb_scan);
    csr_scan3<<<nb_scan, SCAN_B>>>(n_nodes, nnz);
    csr_scatter<<<nb_nnz, T>>>(rows, cols, vals, nnz);

    dsort_hist<<<nb_nod, T>>>(n_nodes);
    dsort_scan<<<1, DBINS>>>();
    dsort_scatter<<<nb_nod, T>>>(n_nodes);

    lgcn_spmm_csr<<<nb_spm, T>>>(0, n_nodes, nullptr);            // layer 1: A->B
    lgcn_spmm_csr<<<nb_spm, T>>>(1, n_nodes, nullptr);            // layer 2: B->A
    lgcn_spmm_csr<<<nb_spm, T>>>(0, n_nodes, (float4*)d_out);     // layer 3 + mean
}